// round 1
// baseline (speedup 1.0000x reference)
#include <cuda_runtime.h>

#define N_MAX   100000
#define E_MAX   1600000
#define NFEAT   128
#define NHID    64
#define NCLS    40

// ---------------- device scratch (allocation-free) ----------------
__device__ int    g_is64;
__device__ int    g_src[E_MAX];
__device__ int    g_dst[E_MAX];
__device__ float  g_cnt[N_MAX];
__device__ float  g_inv[N_MAX];
__device__ float4 g_h1[N_MAX * 16];   // h1  [N,64]
__device__ float4 g_a1[N_MAX * 16];   // agg1[N,64]
__device__ float4 g_h2[N_MAX * 10];   // h2  [N,40]
__device__ float4 g_a2[N_MAX * 10];   // agg2[N,40]

// ---------------- dtype detect: int64 edge_index has zero high words ----
__global__ void k_detect(const unsigned* __restrict__ ei) {
    if (threadIdx.x == 0 && blockIdx.x == 0) {
        unsigned hi = 0;
        #pragma unroll
        for (int i = 1; i < 64; i += 2) hi |= ei[i];
        g_is64 = (hi == 0u) ? 1 : 0;
    }
}

__global__ void k_initcnt(int n) {
    int i = blockIdx.x * blockDim.x + threadIdx.x;
    if (i < n) g_cnt[i] = 1.0f;   // self-loop
}

__global__ void k_extract(const void* __restrict__ ei, int E) {
    int i = blockIdx.x * blockDim.x + threadIdx.x;
    if (i >= E) return;
    int s, d;
    if (g_is64) {
        const long long* p = (const long long*)ei;
        s = (int)p[i]; d = (int)p[E + i];
    } else {
        const int* p = (const int*)ei;
        s = p[i]; d = p[E + i];
    }
    g_src[i] = s;
    g_dst[i] = d;
    atomicAdd(&g_cnt[d], 1.0f);
}

__global__ void k_inv(int n) {
    int i = blockIdx.x * blockDim.x + threadIdx.x;
    if (i < n) g_inv[i] = 1.0f / g_cnt[i];
}

// ---------------- GEMM1: h1 = x @ W1^T + b1   [N,128]x[64,128] -> [N,64]
// 64-row x 64-col tile, 256 threads, 4x4 register tiling, K split in halves.
__global__ __launch_bounds__(256) void k_gemm1(
    const float* __restrict__ x, const float* __restrict__ W,
    const float* __restrict__ b, int n)
{
    __shared__ __align__(16) float xs[64][68];  // xs[k][r]
    __shared__ __align__(16) float ws[64][68];  // ws[k][c]
    int tid  = threadIdx.x;
    int row0 = blockIdx.x * 64;
    int tx = tid & 15, ty = tid >> 4;

    float acc[4][4];
    #pragma unroll
    for (int i = 0; i < 4; ++i)
        #pragma unroll
        for (int j = 0; j < 4; ++j) acc[i][j] = 0.f;

    for (int kk = 0; kk < NFEAT; kk += 64) {
        #pragma unroll
        for (int it = 0; it < 4; ++it) {       // x tile: 64 rows x 16 f4
            int idx = tid + it * 256;
            int r = idx >> 4, k4 = idx & 15;
            float4 v = make_float4(0.f, 0.f, 0.f, 0.f);
            int row = row0 + r;
            if (row < n)
                v = __ldg((const float4*)(x + (size_t)row * NFEAT + kk) + k4);
            xs[k4 * 4 + 0][r] = v.x; xs[k4 * 4 + 1][r] = v.y;
            xs[k4 * 4 + 2][r] = v.z; xs[k4 * 4 + 3][r] = v.w;
        }
        #pragma unroll
        for (int it = 0; it < 4; ++it) {       // W tile: 64 c x 16 f4
            int idx = tid + it * 256;
            int c = idx >> 4, k4 = idx & 15;
            float4 v = __ldg((const float4*)(W + (size_t)c * NFEAT + kk) + k4);
            ws[k4 * 4 + 0][c] = v.x; ws[k4 * 4 + 1][c] = v.y;
            ws[k4 * 4 + 2][c] = v.z; ws[k4 * 4 + 3][c] = v.w;
        }
        __syncthreads();
        #pragma unroll
        for (int k = 0; k < 64; ++k) {
            float4 xv = *(const float4*)&xs[k][ty * 4];
            float4 wv = *(const float4*)&ws[k][tx * 4];
            float ax[4] = {xv.x, xv.y, xv.z, xv.w};
            float aw[4] = {wv.x, wv.y, wv.z, wv.w};
            #pragma unroll
            for (int i = 0; i < 4; ++i)
                #pragma unroll
                for (int j = 0; j < 4; ++j) acc[i][j] += ax[i] * aw[j];
        }
        __syncthreads();
    }

    float4 bb = __ldg((const float4*)b + tx);
    #pragma unroll
    for (int i = 0; i < 4; ++i) {
        int row = row0 + ty * 4 + i;
        if (row < n) {
            float4 o;
            o.x = acc[i][0] + bb.x; o.y = acc[i][1] + bb.y;
            o.z = acc[i][2] + bb.z; o.w = acc[i][3] + bb.w;
            g_h1[row * 16 + tx] = o;   // h1
            g_a1[row * 16 + tx] = o;   // agg1 init = self-loop message
        }
    }
}

// ---------------- scatter 1: agg1[dst] += h1[src]  (half-warp per edge)
__global__ __launch_bounds__(256) void k_scatter1(int E) {
    int t = blockIdx.x * blockDim.x + threadIdx.x;
    int e = t >> 4;
    if (e >= E) return;
    int lane = t & 15;
    int s = __ldg(&g_src[e]);
    int d = __ldg(&g_dst[e]);
    float4 v = __ldg(&g_h1[s * 16 + lane]);
    asm volatile("red.global.add.v4.f32 [%0], {%1,%2,%3,%4};"
                 :: "l"(&g_a1[d * 16 + lane]),
                    "f"(v.x), "f"(v.y), "f"(v.z), "f"(v.w) : "memory");
}

// ---------------- GEMM2: h2 = relu(agg1*inv) @ W2^T + b2  -> [N,40]
// 64-row x 40-col tile, 160 threads, 4x4 tiling, relu/scale fused at load.
__global__ __launch_bounds__(160) void k_gemm2(
    const float* __restrict__ W, const float* __restrict__ b, int n)
{
    __shared__ __align__(16) float rs[64][68];  // rs[k][r]
    __shared__ __align__(16) float ws[64][44];  // ws[k][c]
    int tid  = threadIdx.x;
    int row0 = blockIdx.x * 64;

    for (int idx = tid; idx < 1024; idx += 160) {   // r1 tile
        int r = idx >> 4, k4 = idx & 15;
        int row = row0 + r;
        float4 v = make_float4(0.f, 0.f, 0.f, 0.f);
        if (row < n) {
            float iv = g_inv[row];
            float4 a = g_a1[row * 16 + k4];
            v.x = fmaxf(a.x * iv, 0.f); v.y = fmaxf(a.y * iv, 0.f);
            v.z = fmaxf(a.z * iv, 0.f); v.w = fmaxf(a.w * iv, 0.f);
        }
        rs[k4 * 4 + 0][r] = v.x; rs[k4 * 4 + 1][r] = v.y;
        rs[k4 * 4 + 2][r] = v.z; rs[k4 * 4 + 3][r] = v.w;
    }
    for (int idx = tid; idx < 640; idx += 160) {    // W2: 40 x 16 f4
        int c = idx >> 4, k4 = idx & 15;
        float4 v = __ldg((const float4*)(W + (size_t)c * NHID) + k4);
        ws[k4 * 4 + 0][c] = v.x; ws[k4 * 4 + 1][c] = v.y;
        ws[k4 * 4 + 2][c] = v.z; ws[k4 * 4 + 3][c] = v.w;
    }
    __syncthreads();

    int tx = tid % 10, ty = tid / 10;
    float acc[4][4];
    #pragma unroll
    for (int i = 0; i < 4; ++i)
        #pragma unroll
        for (int j = 0; j < 4; ++j) acc[i][j] = 0.f;

    #pragma unroll
    for (int k = 0; k < 64; ++k) {
        float4 xv = *(const float4*)&rs[k][ty * 4];
        float4 wv = *(const float4*)&ws[k][tx * 4];
        float ax[4] = {xv.x, xv.y, xv.z, xv.w};
        float aw[4] = {wv.x, wv.y, wv.z, wv.w};
        #pragma unroll
        for (int i = 0; i < 4; ++i)
            #pragma unroll
            for (int j = 0; j < 4; ++j) acc[i][j] += ax[i] * aw[j];
    }

    float4 bb = __ldg((const float4*)b + tx);
    #pragma unroll
    for (int i = 0; i < 4; ++i) {
        int row = row0 + ty * 4 + i;
        if (row < n) {
            float4 o;
            o.x = acc[i][0] + bb.x; o.y = acc[i][1] + bb.y;
            o.z = acc[i][2] + bb.z; o.w = acc[i][3] + bb.w;
            g_h2[row * 10 + tx] = o;
            g_a2[row * 10 + tx] = o;
        }
    }
}

// ---------------- scatter 2: agg2[dst] += h2[src]  (10 lanes per edge)
__global__ __launch_bounds__(320) void k_scatter2(int E) {
    int t = blockIdx.x * blockDim.x + threadIdx.x;
    int e = t / 10;
    if (e >= E) return;
    int lane = t % 10;
    int s = __ldg(&g_src[e]);
    int d = __ldg(&g_dst[e]);
    float4 v = __ldg(&g_h2[s * 10 + lane]);
    asm volatile("red.global.add.v4.f32 [%0], {%1,%2,%3,%4};"
                 :: "l"(&g_a2[d * 10 + lane]),
                    "f"(v.x), "f"(v.y), "f"(v.z), "f"(v.w) : "memory");
}

// ---------------- finalize: out = log_softmax(agg2 * inv)  (warp/row)
__global__ __launch_bounds__(256) void k_finalize(float* __restrict__ out, int n) {
    int warp = (blockIdx.x * blockDim.x + threadIdx.x) >> 5;
    int lane = threadIdx.x & 31;
    if (warp >= n) return;
    float iv = g_inv[warp];
    const float* a2 = (const float*)g_a2 + (size_t)warp * NCLS;
    float x0 = a2[lane] * iv;
    float x1 = (lane < 8) ? a2[32 + lane] * iv : -3.4e38f;
    float m = fmaxf(x0, x1);
    #pragma unroll
    for (int o = 16; o > 0; o >>= 1)
        m = fmaxf(m, __shfl_xor_sync(0xFFFFFFFFu, m, o));
    float s = expf(x0 - m) + ((lane < 8) ? expf(x1 - m) : 0.f);
    #pragma unroll
    for (int o = 16; o > 0; o >>= 1)
        s += __shfl_xor_sync(0xFFFFFFFFu, s, o);
    float l = m + logf(s);
    out[(size_t)warp * NCLS + lane] = x0 - l;
    if (lane < 8) out[(size_t)warp * NCLS + 32 + lane] = x1 - l;
}

// ---------------- launch ----------------
extern "C" void kernel_launch(void* const* d_in, const int* in_sizes, int n_in,
                              void* d_out, int out_size)
{
    const float* x  = (const float*)d_in[0];
    const void*  ei = d_in[1];
    const float* W1 = (const float*)d_in[2];
    const float* b1 = (const float*)d_in[3];
    const float* W2 = (const float*)d_in[4];
    const float* b2 = (const float*)d_in[5];
    float* out = (float*)d_out;

    int n = in_sizes[0] / NFEAT;      // 100000
    int E = in_sizes[1] / 2;          // 1600000

    k_detect  <<<1, 32>>>((const unsigned*)ei);
    k_initcnt <<<(n + 255) / 256, 256>>>(n);
    k_extract <<<(E + 255) / 256, 256>>>(ei, E);
    k_inv     <<<(n + 255) / 256, 256>>>(n);

    k_gemm1   <<<(n + 63) / 64, 256>>>(x, W1, b1, n);
    k_scatter1<<<(E * 16 + 255) / 256, 256>>>(E);

    k_gemm2   <<<(n + 63) / 64, 160>>>(W2, b2, n);
    k_scatter2<<<(E * 10 + 319) / 320, 320>>>(E);

    k_finalize<<<(n + 7) / 8, 256>>>(out, n);
}

// round 2
// speedup vs baseline: 1.3787x; 1.3787x over previous
#include <cuda_runtime.h>
#include <cuda_fp16.h>

#define N_MAX   100000
#define E_MAX   1600000
#define NFEAT   128
#define NHID    64
#define NCLS    40

// ---------------- device scratch (allocation-free) ----------------
__device__ int    g_is64;
__device__ int    g_src[E_MAX];
__device__ int    g_dst[E_MAX];
__device__ float  g_cnt[N_MAX];
__device__ uint4  g_h1h[N_MAX * 8];    // h1  [N,64]  fp16
__device__ uint4  g_a1h[N_MAX * 8];    // agg1[N,64]  fp16
__device__ uint4  g_h2h[N_MAX * 5];    // h2  [N,40]  fp16
__device__ uint4  g_a2h[N_MAX * 5];    // agg2[N,40]  fp16

// ---------------- pre: init cnt (self-loop) + dtype detect ----------
__global__ void k_pre(const unsigned* __restrict__ ei, int n) {
    int i = blockIdx.x * blockDim.x + threadIdx.x;
    if (i < n) g_cnt[i] = 1.0f;
    if (i == 0) {
        unsigned hi = 0;
        #pragma unroll
        for (int j = 1; j < 64; j += 2) hi |= ei[j];
        g_is64 = (hi == 0u) ? 1 : 0;
    }
}

// ---------------- extract edges to int32 + degree count ------------
__global__ void k_extract(const void* __restrict__ ei, int E) {
    int i = blockIdx.x * blockDim.x + threadIdx.x;
    if (i >= E) return;
    int s, d;
    if (g_is64) {
        const long long* p = (const long long*)ei;
        s = (int)p[i]; d = (int)p[E + i];
    } else {
        const int* p = (const int*)ei;
        s = p[i]; d = p[E + i];
    }
    g_src[i] = s;
    g_dst[i] = d;
    atomicAdd(&g_cnt[d], 1.0f);
}

// ---------------- GEMM1: h1 = x @ W1^T + b1  [N,128]x[64,128] -> [N,64] fp16
__global__ __launch_bounds__(256) void k_gemm1(
    const float* __restrict__ x, const float* __restrict__ W,
    const float* __restrict__ b, int n)
{
    __shared__ __align__(16) float xs[64][68];  // xs[k][r]
    __shared__ __align__(16) float ws[64][68];  // ws[k][c]
    int tid  = threadIdx.x;
    int row0 = blockIdx.x * 64;
    int tx = tid & 15, ty = tid >> 4;

    float acc[4][4];
    #pragma unroll
    for (int i = 0; i < 4; ++i)
        #pragma unroll
        for (int j = 0; j < 4; ++j) acc[i][j] = 0.f;

    for (int kk = 0; kk < NFEAT; kk += 64) {
        #pragma unroll
        for (int it = 0; it < 4; ++it) {       // x tile: 64 rows x 16 f4
            int idx = tid + it * 256;
            int r = idx >> 4, k4 = idx & 15;
            float4 v = make_float4(0.f, 0.f, 0.f, 0.f);
            int row = row0 + r;
            if (row < n)
                v = __ldg((const float4*)(x + (size_t)row * NFEAT + kk) + k4);
            xs[k4 * 4 + 0][r] = v.x; xs[k4 * 4 + 1][r] = v.y;
            xs[k4 * 4 + 2][r] = v.z; xs[k4 * 4 + 3][r] = v.w;
        }
        #pragma unroll
        for (int it = 0; it < 4; ++it) {       // W tile: 64 c x 16 f4
            int idx = tid + it * 256;
            int c = idx >> 4, k4 = idx & 15;
            float4 v = __ldg((const float4*)(W + (size_t)c * NFEAT + kk) + k4);
            ws[k4 * 4 + 0][c] = v.x; ws[k4 * 4 + 1][c] = v.y;
            ws[k4 * 4 + 2][c] = v.z; ws[k4 * 4 + 3][c] = v.w;
        }
        __syncthreads();
        #pragma unroll
        for (int k = 0; k < 64; ++k) {
            float4 xv = *(const float4*)&xs[k][ty * 4];
            float4 wv = *(const float4*)&ws[k][tx * 4];
            float ax[4] = {xv.x, xv.y, xv.z, xv.w};
            float aw[4] = {wv.x, wv.y, wv.z, wv.w};
            #pragma unroll
            for (int i = 0; i < 4; ++i)
                #pragma unroll
                for (int j = 0; j < 4; ++j) acc[i][j] += ax[i] * aw[j];
        }
        __syncthreads();
    }

    float4 bb = __ldg((const float4*)b + tx);
    #pragma unroll
    for (int i = 0; i < 4; ++i) {
        int row = row0 + ty * 4 + i;
        if (row < n) {
            __half2 p0 = __floats2half2_rn(acc[i][0] + bb.x, acc[i][1] + bb.y);
            __half2 p1 = __floats2half2_rn(acc[i][2] + bb.z, acc[i][3] + bb.w);
            uint2 o;
            o.x = *(unsigned*)&p0; o.y = *(unsigned*)&p1;
            ((uint2*)g_h1h)[row * 16 + tx] = o;   // h1
            ((uint2*)g_a1h)[row * 16 + tx] = o;   // agg1 init = self-loop msg
        }
    }
}

// ---------------- scatter 1: agg1[dst] += h1[src]  (8 lanes/edge, 16B) ----
__global__ __launch_bounds__(256) void k_scatter1(int E) {
    int t = blockIdx.x * blockDim.x + threadIdx.x;
    int e = t >> 3;
    if (e >= E) return;
    int lane = t & 7;
    int s = __ldg(&g_src[e]);
    int d = __ldg(&g_dst[e]);
    uint4 v = __ldg(&g_h1h[s * 8 + lane]);
    asm volatile("red.global.add.noftz.v4.f16x2 [%0], {%1,%2,%3,%4};"
                 :: "l"(&g_a1h[d * 8 + lane]),
                    "r"(v.x), "r"(v.y), "r"(v.z), "r"(v.w) : "memory");
}

// ---------------- GEMM2: h2 = relu(agg1/cnt) @ W2^T + b2  -> [N,40] fp16
__global__ __launch_bounds__(160) void k_gemm2(
    const float* __restrict__ W, const float* __restrict__ b, int n)
{
    __shared__ __align__(16) float rs[64][68];  // rs[k][r]
    __shared__ __align__(16) float ws[64][44];  // ws[k][c]
    int tid  = threadIdx.x;
    int row0 = blockIdx.x * 64;

    for (int idx = tid; idx < 1024; idx += 160) {   // relu(agg1/cnt) tile
        int r = idx >> 4, k4 = idx & 15;
        int row = row0 + r;
        float4 v = make_float4(0.f, 0.f, 0.f, 0.f);
        if (row < n) {
            float iv = 1.0f / __ldg(&g_cnt[row]);
            uint2 a = ((const uint2*)g_a1h)[row * 16 + k4];
            float2 f0 = __half22float2(*(__half2*)&a.x);
            float2 f1 = __half22float2(*(__half2*)&a.y);
            v.x = fmaxf(f0.x * iv, 0.f); v.y = fmaxf(f0.y * iv, 0.f);
            v.z = fmaxf(f1.x * iv, 0.f); v.w = fmaxf(f1.y * iv, 0.f);
        }
        rs[k4 * 4 + 0][r] = v.x; rs[k4 * 4 + 1][r] = v.y;
        rs[k4 * 4 + 2][r] = v.z; rs[k4 * 4 + 3][r] = v.w;
    }
    for (int idx = tid; idx < 640; idx += 160) {    // W2: 40 x 16 f4
        int c = idx >> 4, k4 = idx & 15;
        float4 v = __ldg((const float4*)(W + (size_t)c * NHID) + k4);
        ws[k4 * 4 + 0][c] = v.x; ws[k4 * 4 + 1][c] = v.y;
        ws[k4 * 4 + 2][c] = v.z; ws[k4 * 4 + 3][c] = v.w;
    }
    __syncthreads();

    int tx = tid % 10, ty = tid / 10;
    float acc[4][4];
    #pragma unroll
    for (int i = 0; i < 4; ++i)
        #pragma unroll
        for (int j = 0; j < 4; ++j) acc[i][j] = 0.f;

    #pragma unroll
    for (int k = 0; k < 64; ++k) {
        float4 xv = *(const float4*)&rs[k][ty * 4];
        float4 wv = *(const float4*)&ws[k][tx * 4];
        float ax[4] = {xv.x, xv.y, xv.z, xv.w};
        float aw[4] = {wv.x, wv.y, wv.z, wv.w};
        #pragma unroll
        for (int i = 0; i < 4; ++i)
            #pragma unroll
            for (int j = 0; j < 4; ++j) acc[i][j] += ax[i] * aw[j];
    }

    float4 bb = __ldg((const float4*)b + tx);
    #pragma unroll
    for (int i = 0; i < 4; ++i) {
        int row = row0 + ty * 4 + i;
        if (row < n) {
            __half2 p0 = __floats2half2_rn(acc[i][0] + bb.x, acc[i][1] + bb.y);
            __half2 p1 = __floats2half2_rn(acc[i][2] + bb.z, acc[i][3] + bb.w);
            uint2 o;
            o.x = *(unsigned*)&p0; o.y = *(unsigned*)&p1;
            ((uint2*)g_h2h)[row * 10 + tx] = o;
            ((uint2*)g_a2h)[row * 10 + tx] = o;
        }
    }
}

// ---------------- scatter 2: agg2[dst] += h2[src]  (5 lanes/edge, 16B) ----
__global__ __launch_bounds__(320) void k_scatter2(int E) {
    int t = blockIdx.x * blockDim.x + threadIdx.x;
    int e = t / 5;
    if (e >= E) return;
    int lane = t % 5;
    int s = __ldg(&g_src[e]);
    int d = __ldg(&g_dst[e]);
    uint4 v = __ldg(&g_h2h[s * 5 + lane]);
    asm volatile("red.global.add.noftz.v4.f16x2 [%0], {%1,%2,%3,%4};"
                 :: "l"(&g_a2h[d * 5 + lane]),
                    "r"(v.x), "r"(v.y), "r"(v.z), "r"(v.w) : "memory");
}

// ---------------- finalize: out = log_softmax(agg2/cnt)  (warp/row) ----
__global__ __launch_bounds__(256) void k_finalize(float* __restrict__ out, int n) {
    int row  = (blockIdx.x * blockDim.x + threadIdx.x) >> 5;
    int lane = threadIdx.x & 31;
    if (row >= n) return;
    float x0 = -3.4e38f, x1 = -3.4e38f;
    float iv = 1.0f / g_cnt[row];
    if (lane < 20) {
        unsigned w = ((const unsigned*)g_a2h)[row * 20 + lane];
        float2 f = __half22float2(*(__half2*)&w);
        x0 = f.x * iv; x1 = f.y * iv;
    }
    float m = fmaxf(x0, x1);
    #pragma unroll
    for (int o = 16; o > 0; o >>= 1)
        m = fmaxf(m, __shfl_xor_sync(0xFFFFFFFFu, m, o));
    float s = (lane < 20) ? (expf(x0 - m) + expf(x1 - m)) : 0.f;
    #pragma unroll
    for (int o = 16; o > 0; o >>= 1)
        s += __shfl_xor_sync(0xFFFFFFFFu, s, o);
    float l = m + logf(s);
    if (lane < 20) {
        out[(size_t)row * NCLS + 2 * lane]     = x0 - l;
        out[(size_t)row * NCLS + 2 * lane + 1] = x1 - l;
    }
}

// ---------------- launch ----------------
extern "C" void kernel_launch(void* const* d_in, const int* in_sizes, int n_in,
                              void* d_out, int out_size)
{
    const float* x  = (const float*)d_in[0];
    const void*  ei = d_in[1];
    const float* W1 = (const float*)d_in[2];
    const float* b1 = (const float*)d_in[3];
    const float* W2 = (const float*)d_in[4];
    const float* b2 = (const float*)d_in[5];
    float* out = (float*)d_out;

    int n = in_sizes[0] / NFEAT;      // 100000
    int E = in_sizes[1] / 2;          // 1600000

    k_pre     <<<(n + 255) / 256, 256>>>((const unsigned*)ei, n);
    k_extract <<<(E + 255) / 256, 256>>>(ei, E);

    k_gemm1   <<<(n + 63) / 64, 256>>>(x, W1, b1, n);
    k_scatter1<<<(E * 8 + 255) / 256, 256>>>(E);

    k_gemm2   <<<(n + 63) / 64, 160>>>(W2, b2, n);
    k_scatter2<<<(E * 5 + 319) / 320, 320>>>(E);

    k_finalize<<<(n + 7) / 8, 256>>>(out, n);
}